// round 1
// baseline (speedup 1.0000x reference)
#include <cuda_runtime.h>
#include <cuda_bf16.h>
#include <cstdint>

// INGP hash-grid encoder: 1M points, 16 levels, F=2, T=2^19.
// Thread layout: tid = p*16 + l  (one thread per point-level pair).
//  - coalesced float2 output store: out2[p*16 + l]
//  - 8 independent LDG.64 gathers per thread -> MLP=8 hides L2 latency
// Tables (64 MB) are L2-resident -> L2-BW bound (~4.1 GB of 32B sectors).

#define NLEV 16
#define LOG2T 19
#define TSIZE (1u << LOG2T)
#define TMASK (TSIZE - 1u)

__constant__ float c_res[NLEV] = {
    16.f, 20.f, 25.f, 32.f, 40.f, 50.f, 64.f, 80.f,
    101.f, 128.f, 161.f, 203.f, 256.f, 322.f, 406.f, 512.f
};

__global__ __launch_bounds__(256, 8) void ingp_hash_kernel(
    const float*  __restrict__ x,      // (N,3)
    const float2* __restrict__ emb,    // (16, 2^19) float2
    float2*       __restrict__ out2,   // (N,16) float2  == (N,32) float
    int npts)
{
    int tid = blockIdx.x * blockDim.x + threadIdx.x;
    int p = tid >> 4;
    if (p >= npts) return;
    int l = tid & 15;

    // ---- load + clip point ----
    float px = x[3 * p + 0];
    float py = x[3 * p + 1];
    float pz = x[3 * p + 2];
    px = fminf(fmaxf(px, -1.0f), 1.0f);
    py = fminf(fmaxf(py, -1.0f), 1.0f);
    pz = fminf(fmaxf(pz, -1.0f), 1.0f);

    // ---- voxel + trilinear weights (mirrors reference math) ----
    float res  = c_res[l];
    float grid = 2.0f / res;                 // (BOX_MAX-BOX_MIN)/res

    int bx = __float2int_rd((px + 1.0f) / grid);
    int by = __float2int_rd((py + 1.0f) / grid);
    int bz = __float2int_rd((pz + 1.0f) / grid);

    float wx = (px - ((float)bx * grid - 1.0f)) / grid;
    float wy = (py - ((float)by * grid - 1.0f)) / grid;
    float wz = (pz - ((float)bz * grid - 1.0f)) / grid;

    // ---- factored spatial hash (uint32 wrap semantics) ----
    unsigned hx0 = (unsigned)bx;                         // prime 1
    unsigned hx1 = (unsigned)(bx + 1);
    unsigned hy0 = (unsigned)by       * 2654435761u;
    unsigned hy1 = (unsigned)(by + 1) * 2654435761u;
    unsigned hz0 = (unsigned)bz       * 805459861u;
    unsigned hz1 = (unsigned)(bz + 1) * 805459861u;

    const float2* __restrict__ tbl = emb + (size_t)l * TSIZE;

    // corner bit order: bit2=x, bit1=y, bit0=z (order irrelevant for the sum)
    unsigned i0 = (hx0 ^ hy0 ^ hz0) & TMASK;  // 000
    unsigned i1 = (hx0 ^ hy0 ^ hz1) & TMASK;  // 001
    unsigned i2 = (hx0 ^ hy1 ^ hz0) & TMASK;  // 010
    unsigned i3 = (hx0 ^ hy1 ^ hz1) & TMASK;  // 011
    unsigned i4 = (hx1 ^ hy0 ^ hz0) & TMASK;  // 100
    unsigned i5 = (hx1 ^ hy0 ^ hz1) & TMASK;  // 101
    unsigned i6 = (hx1 ^ hy1 ^ hz0) & TMASK;  // 110
    unsigned i7 = (hx1 ^ hy1 ^ hz1) & TMASK;  // 111

    // ---- 8 independent gathers, front-batched for MLP ----
    float2 e0 = __ldg(tbl + i0);
    float2 e1 = __ldg(tbl + i1);
    float2 e2 = __ldg(tbl + i2);
    float2 e3 = __ldg(tbl + i3);
    float2 e4 = __ldg(tbl + i4);
    float2 e5 = __ldg(tbl + i5);
    float2 e6 = __ldg(tbl + i6);
    float2 e7 = __ldg(tbl + i7);

    // ---- trilinear combine ----
    float ox = 1.0f - wx, oy = 1.0f - wy, oz = 1.0f - wz;
    float w0 = ox * oy * oz;
    float w1 = ox * oy * wz;
    float w2 = ox * wy * oz;
    float w3 = ox * wy * wz;
    float w4 = wx * oy * oz;
    float w5 = wx * oy * wz;
    float w6 = wx * wy * oz;
    float w7 = wx * wy * wz;

    float f0 = w0 * e0.x;
    float f1 = w0 * e0.y;
    f0 = fmaf(w1, e1.x, f0);  f1 = fmaf(w1, e1.y, f1);
    f0 = fmaf(w2, e2.x, f0);  f1 = fmaf(w2, e2.y, f1);
    f0 = fmaf(w3, e3.x, f0);  f1 = fmaf(w3, e3.y, f1);
    f0 = fmaf(w4, e4.x, f0);  f1 = fmaf(w4, e4.y, f1);
    f0 = fmaf(w5, e5.x, f0);  f1 = fmaf(w5, e5.y, f1);
    f0 = fmaf(w6, e6.x, f0);  f1 = fmaf(w6, e6.y, f1);
    f0 = fmaf(w7, e7.x, f0);  f1 = fmaf(w7, e7.y, f1);

    out2[(size_t)p * NLEV + l] = make_float2(f0, f1);
}

extern "C" void kernel_launch(void* const* d_in, const int* in_sizes, int n_in,
                              void* d_out, int out_size)
{
    const float*  x   = (const float*)d_in[0];
    const float2* emb = (const float2*)d_in[1];
    float2*       out = (float2*)d_out;

    int npts = in_sizes[0] / 3;
    long long total = (long long)npts * NLEV;
    int threads = 256;
    int blocks = (int)((total + threads - 1) / threads);

    ingp_hash_kernel<<<blocks, threads>>>(x, emb, out, npts);
}